// round 5
// baseline (speedup 1.0000x reference)
#include <cuda_runtime.h>
#include <stdint.h>

#define NN 16384
#define DD 32
#define LCAP 256          // per-node list capacity (Poisson(64) max-degree safe)
#define BMW (NN / 32)     // 512 u32 = 2KB shared bitmap per warp/row

// Non-deduped adjacency lists (dedup happens in agg via smem bitmap).
__device__ int g_list[(size_t)NN * LCAP];
__device__ int g_cnt[NN];   // zero at load; agg resets each launch

__global__ void __launch_bounds__(256) build_kernel(const int* __restrict__ src,
                                                    const int* __restrict__ dst,
                                                    int E) {
    int e = blockIdx.x * blockDim.x + threadIdx.x;
    if (e >= E) return;
    int s = __ldg(src + e);
    int d = __ldg(dst + e);
    int p = atomicAdd(&g_cnt[s], 1);
    if (p < LCAP) g_list[(size_t)s * LCAP + p] = d;
    p = atomicAdd(&g_cnt[d], 1);
    if (p < LCAP) g_list[(size_t)d * LCAP + p] = s;
}

// One warp per node. Dedup via per-warp 2KB smem bitmap (test-and-set while
// preloading indices; keep-flag packed in bit 31, applied as FFMA weight).
// Gather: 4 lane-groups of 8; one LDG.128 covers 4 neighbor rows.
__global__ void __launch_bounds__(256) agg_kernel(const float* __restrict__ x,
                                                  const float* __restrict__ W_agg,
                                                  const float* __restrict__ b_agg,
                                                  const float* __restrict__ W_upd,
                                                  const float* __restrict__ b_upd,
                                                  float* __restrict__ out) {
    __shared__ float    WaggT[DD * DD];   // [d][c] = W_agg[c][d]
    __shared__ float    WupdT[DD * DD];
    __shared__ float    bsum[DD];
    __shared__ uint32_t bmap[8][BMW];     // 16 KB: dedup bitmap, one per warp
    __shared__ float    msgsm[8][DD];
    __shared__ float    xsm[8][DD];

    int tid = threadIdx.x;
    for (int i = tid; i < DD * DD; i += blockDim.x) {
        int c = i >> 5, d = i & 31;
        WaggT[d * DD + c] = W_agg[i];
        WupdT[d * DD + c] = W_upd[i];
    }
    if (tid < DD) bsum[tid] = b_agg[tid] + b_upd[tid];

    int warp = tid >> 5;
    int lane = tid & 31;
    int row  = blockIdx.x * 8 + warp;

    // Zero this warp's bitmap (2KB = 128 uint4).
    {
        uint4* bz = reinterpret_cast<uint4*>(bmap[warp]);
        const uint4 z = make_uint4(0u, 0u, 0u, 0u);
        bz[lane] = z; bz[lane + 32] = z; bz[lane + 64] = z; bz[lane + 96] = z;
    }
    __syncthreads();   // weights + bitmap ready

    int cnt = g_cnt[row];
    cnt = cnt < LCAP ? cnt : LCAP;
    if (lane == 0) g_cnt[row] = 0;

    const int* lst = g_list + (size_t)row * LCAP;
    int g = lane >> 3;        // gather group 0..3
    int q = lane & 7;         // float4 slot within a 128B row

    // Preload + dedup: lane L owns entries L, L+32, ..., L+224.
    // pk[k] = neighbor_id | (keep << 31)
    unsigned pk[8];
#pragma unroll
    for (int k = 0; k < 8; k++) {
        int pos = (k << 5) + lane;
        unsigned pv = 0u;
        if (pos < cnt) {
            int j = __ldg(lst + pos);
            unsigned bit = 1u << (j & 31);
            unsigned old = atomicOr(&bmap[warp][j >> 5], bit);
            pv = (unsigned)j | ((old & bit) ? 0u : 0x80000000u);
        }
        pk[k] = pv;
    }

    const float4* x4 = reinterpret_cast<const float4*>(x);
    float4 A0 = make_float4(0.f, 0.f, 0.f, 0.f);
    float4 A1 = A0, A2 = A0, A3 = A0;

#pragma unroll
    for (int k = 0; k < 8; k++) {
        if ((k << 5) >= cnt) break;           // warp-uniform
#pragma unroll
        for (int u = 0; u < 8; u++) {
            unsigned p = __shfl_sync(0xffffffffu, pk[k], (u << 2) + g);
            float w = (float)(p >> 31);       // 0 or 1
            int   j = (int)(p & 0x3FFFu);
            float4 v = x4[(size_t)j * 8 + q];
            float4& A = (u & 3) == 0 ? A0 : (u & 3) == 1 ? A1 : (u & 3) == 2 ? A2 : A3;
            A.x = fmaf(w, v.x, A.x);
            A.y = fmaf(w, v.y, A.y);
            A.z = fmaf(w, v.z, A.z);
            A.w = fmaf(w, v.w, A.w);
        }
    }

    // Reduce 4 accumulators, then across the 4 lane-groups.
    float4 s;
    s.x = (A0.x + A1.x) + (A2.x + A3.x);
    s.y = (A0.y + A1.y) + (A2.y + A3.y);
    s.z = (A0.z + A1.z) + (A2.z + A3.z);
    s.w = (A0.w + A1.w) + (A2.w + A3.w);
#pragma unroll
    for (int off = 8; off <= 16; off <<= 1) {
        s.x += __shfl_xor_sync(0xffffffffu, s.x, off);
        s.y += __shfl_xor_sync(0xffffffffu, s.y, off);
        s.z += __shfl_xor_sync(0xffffffffu, s.z, off);
        s.w += __shfl_xor_sync(0xffffffffu, s.w, off);
    }
    if (lane < 8)
        *reinterpret_cast<float4*>(&msgsm[warp][q << 2]) = s;
    xsm[warp][lane] = x[(size_t)row * DD + lane];
    __syncwarp();

    // Fused epilogue: out[row][c] = sum_d msg[d]*W_agg[c][d] + x[row][d]*W_upd[c][d] + b
    float o = bsum[lane];
#pragma unroll
    for (int d = 0; d < DD; d++) {
        o = fmaf(msgsm[warp][d], WaggT[d * DD + lane],
            fmaf(xsm[warp][d],  WupdT[d * DD + lane], o));
    }
    out[(size_t)row * DD + lane] = o;
}

extern "C" void kernel_launch(void* const* d_in, const int* in_sizes, int n_in,
                              void* d_out, int out_size) {
    const float* x     = (const float*)d_in[0];
    const int*   ei    = (const int*)d_in[1];     // [2, E]: row0=src, row1=dst
    const float* W_agg = (const float*)d_in[2];
    const float* b_agg = (const float*)d_in[3];
    const float* W_upd = (const float*)d_in[4];
    const float* b_upd = (const float*)d_in[5];
    float* out = (float*)d_out;

    int E = in_sizes[1] / 2;

    build_kernel<<<(E + 255) / 256, 256>>>(ei, ei + E, E);
    agg_kernel<<<NN / 8, 256>>>(x, W_agg, b_agg, W_upd, b_upd, out);
}

// round 6
// speedup vs baseline: 1.0301x; 1.0301x over previous
#include <cuda_runtime.h>
#include <stdint.h>

#define NN 16384
#define DD 32
#define WPR (NN / 32)     // 512 u32 per dedup-bitmask row
#define LCAP 256          // per-node list capacity (Poisson(64) tail safe)

// Dedup bitmask (32 MB) + deduped adjacency lists + counters.
// Zero at module load; clean_kernel restores zero state every launch.
__device__ uint32_t g_bits[(size_t)NN * WPR];
__device__ int g_list[(size_t)NN * LCAP];
__device__ int g_cnt[NN];

__global__ void __launch_bounds__(256) build_kernel(const int* __restrict__ src,
                                                    const int* __restrict__ dst,
                                                    int E) {
    int e = blockIdx.x * blockDim.x + threadIdx.x;
    if (e >= E) return;
    int s = __ldg(src + e);
    int d = __ldg(dst + e);

    unsigned bd = 1u << (d & 31);
    unsigned old = atomicOr(&g_bits[(size_t)s * WPR + (d >> 5)], bd);
    if (!(old & bd)) {
        int p = atomicAdd(&g_cnt[s], 1);
        if (p < LCAP) g_list[(size_t)s * LCAP + p] = d;
    }

    unsigned bs = 1u << (s & 31);
    old = atomicOr(&g_bits[(size_t)d * WPR + (s >> 5)], bs);
    if (!(old & bs)) {
        int p = atomicAdd(&g_cnt[d], 1);
        if (p < LCAP) g_list[(size_t)d * LCAP + p] = s;
    }
}

// One warp per node, gather + fused epilogue ONLY (no state cleanup here).
// Gather: 4 lane-groups of 8; one LDG.128 covers 4 neighbor rows (float4/lane).
// Tail handled branchlessly via zero-weight padding.
__global__ void __launch_bounds__(256, 6) agg_kernel(const float* __restrict__ x,
                                                     const float* __restrict__ W_agg,
                                                     const float* __restrict__ b_agg,
                                                     const float* __restrict__ W_upd,
                                                     const float* __restrict__ b_upd,
                                                     float* __restrict__ out) {
    __shared__ float WaggT[DD * DD];   // [d][c] = W_agg[c][d]
    __shared__ float WupdT[DD * DD];
    __shared__ float bsum[DD];
    __shared__ float msgsm[8][DD];
    __shared__ float xsm[8][DD];

    int tid = threadIdx.x;
    for (int i = tid; i < DD * DD; i += blockDim.x) {
        int c = i >> 5, d = i & 31;
        WaggT[d * DD + c] = W_agg[i];
        WupdT[d * DD + c] = W_upd[i];
    }
    if (tid < DD) bsum[tid] = b_agg[tid] + b_upd[tid];
    __syncthreads();

    int warp = tid >> 5;
    int lane = tid & 31;
    int row  = blockIdx.x * 8 + warp;

    int cnt = g_cnt[row];                 // uniform broadcast load
    cnt = cnt < LCAP ? cnt : LCAP;
    xsm[warp][lane] = x[(size_t)row * DD + lane];   // prefetch own row early

    const int* lst = g_list + (size_t)row * LCAP;
    int g = lane >> 3;        // gather group 0..3
    int q = lane & 7;         // float4 slot within a 128B row

    // Preload all (guarded) indices: lane L holds entries L, L+32, ..., L+224.
    int idx[8];
#pragma unroll
    for (int k = 0; k < 8; k++)
        idx[k] = ((k << 5) + lane < cnt) ? __ldg(lst + (k << 5) + lane) : 0;

    const float4* x4 = reinterpret_cast<const float4*>(x);
    float4 A0 = make_float4(0.f, 0.f, 0.f, 0.f);
    float4 A1 = A0;

#pragma unroll
    for (int k = 0; k < 8; k++) {
        int base = k << 5;
        if (base >= cnt) break;               // warp-uniform
        int ng = cnt - base;  ng = ng > 32 ? 32 : ng;
        int nu = (ng + 3) >> 2;               // gathers this chunk (pad to 4)
#pragma unroll
        for (int u = 0; u < 8; u++) {
            if (u < nu) {
                int slot = (u << 2) + g;
                int j = __shfl_sync(0xffffffffu, idx[k], slot);
                float w = (slot < ng) ? 1.0f : 0.0f;   // zero-weight padding
                float4 v = x4[(size_t)j * 8 + q];
                float4& A = (u & 1) ? A1 : A0;
                A.x = fmaf(w, v.x, A.x);
                A.y = fmaf(w, v.y, A.y);
                A.z = fmaf(w, v.z, A.z);
                A.w = fmaf(w, v.w, A.w);
            }
        }
    }

    // Reduce 2 accumulators, then across the 4 lane-groups (xor 8, xor 16).
    float4 s;
    s.x = A0.x + A1.x;  s.y = A0.y + A1.y;
    s.z = A0.z + A1.z;  s.w = A0.w + A1.w;
#pragma unroll
    for (int off = 8; off <= 16; off <<= 1) {
        s.x += __shfl_xor_sync(0xffffffffu, s.x, off);
        s.y += __shfl_xor_sync(0xffffffffu, s.y, off);
        s.z += __shfl_xor_sync(0xffffffffu, s.z, off);
        s.w += __shfl_xor_sync(0xffffffffu, s.w, off);
    }
    if (lane < 8)
        *reinterpret_cast<float4*>(&msgsm[warp][q << 2]) = s;
    __syncwarp();

    // Fused epilogue: out[row][c] = sum_d msg[d]*W_agg[c][d] + x[row][d]*W_upd[c][d] + b
    float o = bsum[lane];
#pragma unroll
    for (int d = 0; d < DD; d++) {
        o = fmaf(msgsm[warp][d], WaggT[d * DD + lane],
            fmaf(xsm[warp][d],  WupdT[d * DD + lane], o));
    }
    out[(size_t)row * DD + lane] = o;
}

// Restore clean state for the next graph replay: zero bitmask + counters.
// Linear 32MB memset, L2-write-throughput bound (~2.6us).
__global__ void __launch_bounds__(256) clean_kernel() {
    unsigned t = blockIdx.x * 256u + threadIdx.x;       // 524288 threads
    uint4* B = reinterpret_cast<uint4*>(g_bits);        // 2M uint4 total
    const uint4 z = make_uint4(0u, 0u, 0u, 0u);
    B[t]             = z;
    B[t + 524288u]   = z;
    B[t + 1048576u]  = z;
    B[t + 1572864u]  = z;
    if (t < NN) g_cnt[t] = 0;
}

extern "C" void kernel_launch(void* const* d_in, const int* in_sizes, int n_in,
                              void* d_out, int out_size) {
    const float* x     = (const float*)d_in[0];
    const int*   ei    = (const int*)d_in[1];     // [2, E]: row0=src, row1=dst
    const float* W_agg = (const float*)d_in[2];
    const float* b_agg = (const float*)d_in[3];
    const float* W_upd = (const float*)d_in[4];
    const float* b_upd = (const float*)d_in[5];
    float* out = (float*)d_out;

    int E = in_sizes[1] / 2;

    build_kernel<<<(E + 255) / 256, 256>>>(ei, ei + E, E);
    agg_kernel<<<NN / 8, 256>>>(x, W_agg, b_agg, W_upd, b_upd, out);
    clean_kernel<<<2048, 256>>>();
}

// round 7
// speedup vs baseline: 1.0667x; 1.0355x over previous
#include <cuda_runtime.h>
#include <stdint.h>

#define NN 16384
#define DD 32
#define WPR (NN / 32)     // 512 u32 per dedup-bitmask row
#define LCAP 256          // per-node list capacity (Poisson(64) tail safe)

// Dedup bitmask (32 MB) + deduped adjacency lists + counters.
// Zero at module load; agg_kernel restores zero state every launch.
__device__ uint32_t g_bits[(size_t)NN * WPR];
__device__ int g_list[(size_t)NN * LCAP];
__device__ int g_cnt[NN];

// 4 edges per thread: 2x LDG.128 for indices, then 8 INDEPENDENT atomicOr
// issued before any dependent consumer -> 4x memory-level parallelism.
__global__ void __launch_bounds__(256) build_kernel(const int* __restrict__ src,
                                                    const int* __restrict__ dst,
                                                    int E4) {
    int t = blockIdx.x * blockDim.x + threadIdx.x;
    if (t >= E4) return;
    int4 s4 = __ldg(reinterpret_cast<const int4*>(src) + t);
    int4 d4 = __ldg(reinterpret_cast<const int4*>(dst) + t);

    int s[4] = {s4.x, s4.y, s4.z, s4.w};
    int d[4] = {d4.x, d4.y, d4.z, d4.w};

    unsigned oldf[4], oldb[4];
#pragma unroll
    for (int i = 0; i < 4; i++)
        oldf[i] = atomicOr(&g_bits[(size_t)s[i] * WPR + (d[i] >> 5)], 1u << (d[i] & 31));
#pragma unroll
    for (int i = 0; i < 4; i++)
        oldb[i] = atomicOr(&g_bits[(size_t)d[i] * WPR + (s[i] >> 5)], 1u << (s[i] & 31));

#pragma unroll
    for (int i = 0; i < 4; i++) {
        if (!(oldf[i] & (1u << (d[i] & 31)))) {
            int p = atomicAdd(&g_cnt[s[i]], 1);
            if (p < LCAP) g_list[(size_t)s[i] * LCAP + p] = d[i];
        }
        if (!(oldb[i] & (1u << (s[i] & 31)))) {
            int p = atomicAdd(&g_cnt[d[i]], 1);
            if (p < LCAP) g_list[(size_t)d[i] * LCAP + p] = s[i];
        }
    }
}

// One warp per node. Gather (4 lane-groups of 8, one LDG.128 = 4 neighbor rows),
// state cleanup folded in after gathers are in flight, fused 32x32 epilogue.
__global__ void __launch_bounds__(256, 6) agg_kernel(const float* __restrict__ x,
                                                     const float* __restrict__ W_agg,
                                                     const float* __restrict__ b_agg,
                                                     const float* __restrict__ W_upd,
                                                     const float* __restrict__ b_upd,
                                                     float* __restrict__ out) {
    __shared__ float WaggT[DD * DD];   // [d][c] = W_agg[c][d]
    __shared__ float WupdT[DD * DD];
    __shared__ float bsum[DD];
    __shared__ float msgsm[8][DD];
    __shared__ float xsm[8][DD];

    int tid = threadIdx.x;
    for (int i = tid; i < DD * DD; i += blockDim.x) {
        int c = i >> 5, d = i & 31;
        WaggT[d * DD + c] = W_agg[i];
        WupdT[d * DD + c] = W_upd[i];
    }
    if (tid < DD) bsum[tid] = b_agg[tid] + b_upd[tid];
    __syncthreads();

    int warp = tid >> 5;
    int lane = tid & 31;
    int row  = blockIdx.x * 8 + warp;

    int cnt = g_cnt[row];                 // uniform broadcast load
    cnt = cnt < LCAP ? cnt : LCAP;
    if (lane == 0) g_cnt[row] = 0;        // reset for next replay
    xsm[warp][lane] = x[(size_t)row * DD + lane];   // prefetch own row early

    const int* lst = g_list + (size_t)row * LCAP;
    int g = lane >> 3;        // gather group 0..3
    int q = lane & 7;         // float4 slot within a 128B row

    // Preload all (guarded) indices: lane L holds entries L, L+32, ..., L+224.
    int idx[8];
#pragma unroll
    for (int k = 0; k < 8; k++)
        idx[k] = ((k << 5) + lane < cnt) ? __ldg(lst + (k << 5) + lane) : 0;

    const float4* x4 = reinterpret_cast<const float4*>(x);
    float4 A0 = make_float4(0.f, 0.f, 0.f, 0.f);
    float4 A1 = A0;

#pragma unroll
    for (int k = 0; k < 8; k++) {
        int base = k << 5;
        if (base >= cnt) break;               // warp-uniform
        int ng = cnt - base;  ng = ng > 32 ? 32 : ng;
        int nu = (ng + 3) >> 2;               // gathers this chunk (pad to 4)
#pragma unroll
        for (int u = 0; u < 8; u++) {
            if (u < nu) {
                int slot = (u << 2) + g;
                int j = __shfl_sync(0xffffffffu, idx[k], slot);
                float w = (slot < ng) ? 1.0f : 0.0f;   // zero-weight padding
                float4 v = x4[(size_t)j * 8 + q];
                float4& A = (u & 1) ? A1 : A0;
                A.x = fmaf(w, v.x, A.x);
                A.y = fmaf(w, v.y, A.y);
                A.z = fmaf(w, v.z, A.z);
                A.w = fmaf(w, v.w, A.w);
            }
        }
    }

    // Clear this row's dedup bits for the next replay (gathers already issued).
    {
        uint4* rv = reinterpret_cast<uint4*>(g_bits + (size_t)row * WPR);
        const uint4 z = make_uint4(0u, 0u, 0u, 0u);
        rv[lane]      = z;
        rv[lane + 32] = z;
        rv[lane + 64] = z;
        rv[lane + 96] = z;
    }

    // Reduce 2 accumulators, then across the 4 lane-groups (xor 8, xor 16).
    float4 s;
    s.x = A0.x + A1.x;  s.y = A0.y + A1.y;
    s.z = A0.z + A1.z;  s.w = A0.w + A1.w;
#pragma unroll
    for (int off = 8; off <= 16; off <<= 1) {
        s.x += __shfl_xor_sync(0xffffffffu, s.x, off);
        s.y += __shfl_xor_sync(0xffffffffu, s.y, off);
        s.z += __shfl_xor_sync(0xffffffffu, s.z, off);
        s.w += __shfl_xor_sync(0xffffffffu, s.w, off);
    }
    if (lane < 8)
        *reinterpret_cast<float4*>(&msgsm[warp][q << 2]) = s;
    __syncwarp();

    // Fused epilogue: out[row][c] = sum_d msg[d]*W_agg[c][d] + x[row][d]*W_upd[c][d] + b
    float o = bsum[lane];
#pragma unroll
    for (int d = 0; d < DD; d++) {
        o = fmaf(msgsm[warp][d], WaggT[d * DD + lane],
            fmaf(xsm[warp][d],  WupdT[d * DD + lane], o));
    }
    out[(size_t)row * DD + lane] = o;
}

extern "C" void kernel_launch(void* const* d_in, const int* in_sizes, int n_in,
                              void* d_out, int out_size) {
    const float* x     = (const float*)d_in[0];
    const int*   ei    = (const int*)d_in[1];     // [2, E]: row0=src, row1=dst
    const float* W_agg = (const float*)d_in[2];
    const float* b_agg = (const float*)d_in[3];
    const float* W_upd = (const float*)d_in[4];
    const float* b_upd = (const float*)d_in[5];
    float* out = (float*)d_out;

    int E  = in_sizes[1] / 2;
    int E4 = E / 4;                               // E = 524288, divisible by 4

    build_kernel<<<(E4 + 255) / 256, 256>>>(ei, ei + E, E4);
    agg_kernel<<<NN / 8, 256>>>(x, W_agg, b_agg, W_upd, b_upd, out);
}

// round 8
// speedup vs baseline: 1.1218x; 1.0517x over previous
#include <cuda_runtime.h>
#include <stdint.h>

#define NN 16384
#define DD 32
#define WPR (NN / 32)     // 512 u32 per dedup-bitmask row
#define LCAP 256          // per-node list capacity

// Dedup bitmask (32 MB) + deduped adjacency lists + counters.
// Zero at module load; agg_kernel restores bitmask+counter state every launch.
// g_list is intentionally NOT cleared: it only ever holds valid node ids
// (< NN), and entries beyond g_cnt are masked by zero-weight in agg.
__device__ uint32_t g_bits[(size_t)NN * WPR];
__device__ int g_list[(size_t)NN * LCAP];
__device__ int g_cnt[NN];

// 8 edges per thread: 4x LDG.128 index loads, 16 INDEPENDENT atomicOr
// issued back-to-back before any dependent consumer (MLP=16).
__global__ void __launch_bounds__(256) build_kernel(const int* __restrict__ src,
                                                    const int* __restrict__ dst,
                                                    int E8) {
    int t = blockIdx.x * blockDim.x + threadIdx.x;
    if (t >= E8) return;
    int4 sa = __ldg(reinterpret_cast<const int4*>(src) + 2 * t);
    int4 sb = __ldg(reinterpret_cast<const int4*>(src) + 2 * t + 1);
    int4 da = __ldg(reinterpret_cast<const int4*>(dst) + 2 * t);
    int4 db = __ldg(reinterpret_cast<const int4*>(dst) + 2 * t + 1);

    int s[8] = {sa.x, sa.y, sa.z, sa.w, sb.x, sb.y, sb.z, sb.w};
    int d[8] = {da.x, da.y, da.z, da.w, db.x, db.y, db.z, db.w};

    unsigned oldf[8], oldb[8];
#pragma unroll
    for (int i = 0; i < 8; i++)
        oldf[i] = atomicOr(&g_bits[(size_t)s[i] * WPR + (d[i] >> 5)], 1u << (d[i] & 31));
#pragma unroll
    for (int i = 0; i < 8; i++)
        oldb[i] = atomicOr(&g_bits[(size_t)d[i] * WPR + (s[i] >> 5)], 1u << (s[i] & 31));

#pragma unroll
    for (int i = 0; i < 8; i++) {
        if (!(oldf[i] & (1u << (d[i] & 31)))) {
            int p = atomicAdd(&g_cnt[s[i]], 1);
            if (p < LCAP) g_list[(size_t)s[i] * LCAP + p] = d[i];
        }
        if (!(oldb[i] & (1u << (s[i] & 31)))) {
            int p = atomicAdd(&g_cnt[d[i]], 1);
            if (p < LCAP) g_list[(size_t)d[i] * LCAP + p] = s[i];
        }
    }
}

// One warp per node. Indices for slots 0..95 loaded UNGUARDED at entry
// (list entries are always valid node ids; stale ones get weight 0), so no
// address depends on g_cnt. Gather: 4 lane-groups of 8, one LDG.128 = 4
// neighbor rows; slots 0..63 fully branchless (16 independent LDGs in one
// straight-line block -> MLP 16).
__global__ void __launch_bounds__(256, 6) agg_kernel(const float* __restrict__ x,
                                                     const float* __restrict__ W_agg,
                                                     const float* __restrict__ b_agg,
                                                     const float* __restrict__ W_upd,
                                                     const float* __restrict__ b_upd,
                                                     float* __restrict__ out) {
    __shared__ float WaggT[DD * DD];   // [d][c] = W_agg[c][d]
    __shared__ float WupdT[DD * DD];
    __shared__ float bsum[DD];
    __shared__ float msgsm[8][DD];
    __shared__ float xsm[8][DD];

    int tid  = threadIdx.x;
    int warp = tid >> 5;
    int lane = tid & 31;
    int row  = blockIdx.x * 8 + warp;

    const int* lst = g_list + (size_t)row * LCAP;

    // Front-batched independent loads: 3 index words + own x row + cnt.
    int i0 = __ldg(lst + lane);
    int i1 = __ldg(lst + 32 + lane);
    int i2 = __ldg(lst + 64 + lane);
    float xown = x[(size_t)row * DD + lane];
    int cnt = g_cnt[row];
    cnt = cnt < LCAP ? cnt : LCAP;
    if (lane == 0) g_cnt[row] = 0;        // reset for next replay

    for (int i = tid; i < DD * DD; i += blockDim.x) {
        int c = i >> 5, d = i & 31;
        WaggT[d * DD + c] = W_agg[i];
        WupdT[d * DD + c] = W_upd[i];
    }
    if (tid < DD) bsum[tid] = b_agg[tid] + b_upd[tid];

    int g = lane >> 3;        // gather group 0..3
    int q = lane & 7;         // float4 slot within a 128B row

    const float4* x4 = reinterpret_cast<const float4*>(x);
    float4 A0 = make_float4(0.f, 0.f, 0.f, 0.f);
    float4 A1 = A0;

    // ---- Block 1: slots 0..63, fully branchless (16 independent LDG.128).
#pragma unroll
    for (int u = 0; u < 8; u++) {
        int slot = (u << 2) + g;
        int j = __shfl_sync(0xffffffffu, i0, slot);
        float w = (slot < cnt) ? 1.0f : 0.0f;
        float4 v = x4[(size_t)j * 8 + q];
        float4& A = (u & 1) ? A1 : A0;
        A.x = fmaf(w, v.x, A.x); A.y = fmaf(w, v.y, A.y);
        A.z = fmaf(w, v.z, A.z); A.w = fmaf(w, v.w, A.w);
    }
#pragma unroll
    for (int u = 0; u < 8; u++) {
        int slot = (u << 2) + g;
        int j = __shfl_sync(0xffffffffu, i1, slot);
        float w = (32 + slot < cnt) ? 1.0f : 0.0f;
        float4 v = x4[(size_t)j * 8 + q];
        float4& A = (u & 1) ? A1 : A0;
        A.x = fmaf(w, v.x, A.x); A.y = fmaf(w, v.y, A.y);
        A.z = fmaf(w, v.z, A.z); A.w = fmaf(w, v.w, A.w);
    }

    // ---- Block 2: slots 64..95 (47% of rows enter; nu-granular).
    if (cnt > 64) {
        int ng = cnt - 64;  ng = ng > 32 ? 32 : ng;
        int nu = (ng + 3) >> 2;
#pragma unroll
        for (int u = 0; u < 8; u++) {
            if (u < nu) {
                int slot = (u << 2) + g;
                int j = __shfl_sync(0xffffffffu, i2, slot);
                float w = (slot < ng) ? 1.0f : 0.0f;
                float4 v = x4[(size_t)j * 8 + q];
                float4& A = (u & 1) ? A1 : A0;
                A.x = fmaf(w, v.x, A.x); A.y = fmaf(w, v.y, A.y);
                A.z = fmaf(w, v.z, A.z); A.w = fmaf(w, v.w, A.w);
            }
        }
    }

    // ---- Rare tail: slots 96..255 (Poisson(64) -> ~never; kept for correctness).
    for (int k = 3; k < 8; k++) {
        int base = k << 5;
        if (base >= cnt) break;
        int ik = __ldg(lst + base + lane);
        int ng = cnt - base;  ng = ng > 32 ? 32 : ng;
        int nu = (ng + 3) >> 2;
        for (int u = 0; u < 8; u++) {
            if (u < nu) {
                int slot = (u << 2) + g;
                int j = __shfl_sync(0xffffffffu, ik, slot);
                float w = (slot < ng) ? 1.0f : 0.0f;
                float4 v = x4[(size_t)j * 8 + q];
                A0.x = fmaf(w, v.x, A0.x); A0.y = fmaf(w, v.y, A0.y);
                A0.z = fmaf(w, v.z, A0.z); A0.w = fmaf(w, v.w, A0.w);
            }
        }
    }

    // Clear this row's dedup bits for the next replay (gathers already issued).
    {
        uint4* rv = reinterpret_cast<uint4*>(g_bits + (size_t)row * WPR);
        const uint4 z = make_uint4(0u, 0u, 0u, 0u);
        rv[lane]      = z;
        rv[lane + 32] = z;
        rv[lane + 64] = z;
        rv[lane + 96] = z;
    }

    __syncthreads();   // weights/bias smem ready (overlapped with gather latency)

    // Reduce 2 accumulators, then across the 4 lane-groups (xor 8, xor 16).
    float4 s;
    s.x = A0.x + A1.x;  s.y = A0.y + A1.y;
    s.z = A0.z + A1.z;  s.w = A0.w + A1.w;
#pragma unroll
    for (int off = 8; off <= 16; off <<= 1) {
        s.x += __shfl_xor_sync(0xffffffffu, s.x, off);
        s.y += __shfl_xor_sync(0xffffffffu, s.y, off);
        s.z += __shfl_xor_sync(0xffffffffu, s.z, off);
        s.w += __shfl_xor_sync(0xffffffffu, s.w, off);
    }
    if (lane < 8)
        *reinterpret_cast<float4*>(&msgsm[warp][q << 2]) = s;
    xsm[warp][lane] = xown;
    __syncwarp();

    // Fused epilogue: out[row][c] = sum_d msg[d]*W_agg[c][d] + x[row][d]*W_upd[c][d] + b
    float o = bsum[lane];
#pragma unroll
    for (int d = 0; d < DD; d++) {
        o = fmaf(msgsm[warp][d], WaggT[d * DD + lane],
            fmaf(xsm[warp][d],  WupdT[d * DD + lane], o));
    }
    out[(size_t)row * DD + lane] = o;
}

extern "C" void kernel_launch(void* const* d_in, const int* in_sizes, int n_in,
                              void* d_out, int out_size) {
    const float* x     = (const float*)d_in[0];
    const int*   ei    = (const int*)d_in[1];     // [2, E]: row0=src, row1=dst
    const float* W_agg = (const float*)d_in[2];
    const float* b_agg = (const float*)d_in[3];
    const float* W_upd = (const float*)d_in[4];
    const float* b_upd = (const float*)d_in[5];
    float* out = (float*)d_out;

    int E  = in_sizes[1] / 2;
    int E8 = E / 8;                               // E = 524288, divisible by 8

    build_kernel<<<(E8 + 255) / 256, 256>>>(ei, ei + E, E8);
    agg_kernel<<<NN / 8, 256>>>(x, W_agg, b_agg, W_upd, b_upd, out);
}